// round 14
// baseline (speedup 1.0000x reference)
#include <cuda_runtime.h>

#define WL_L      2048
#define WL_LMASK  2047
#define WL_Q      512                 // quads per plane (L/4)
#define WL_QMASK  511
#define WL_D      32
#define WL_B      16
#define WL_NT     512                 // one thread per output quad

__global__ __launch_bounds__(WL_NT, 3) void wavelet_db4_kernel(
    const float* __restrict__ x,       // (B, L, D)
    const float* __restrict__ w_dec,   // (4, L, L) — only 8 taps read
    const float* __restrict__ v_dec,   // (4, L, L) — only 8 taps read
    float* __restrict__ out)           // (B, D, L, 5)
{
    // full-L plane buffers; rotated for w-staging after their last read:
    //   xs:  x       (read st1)  → holds w0 after stage 2
    //   v0s: v0      (read st2)  → holds w1 after stage 3
    //   v1s: v1      (read st3)
    //   v2s: v2      (read st4)
    __shared__ __align__(16) float xs [WL_L];
    __shared__ __align__(16) float v0s[WL_L];
    __shared__ __align__(16) float v1s[WL_L];
    __shared__ __align__(16) float v2s[WL_L];
    __shared__ float gs[8];
    __shared__ float hs[8];

    const int tid = threadIdx.x;       // quad index 0..511; outputs m=4*tid..+3
    const int bd  = blockIdx.x;        // b*32 + d
    const int b   = bd >> 5;
    const int d   = bd & 31;

    // taps from row 0 of level-0 filters: f[0][0][(0-i) mod L] = tap[i]
    if (tid < 8) {
        int col = (WL_L - tid) & WL_LMASK;
        gs[tid] = v_dec[col];
        hs[tid] = w_dec[col];
    }

    // gather x[b, :, d] (stride-D column; 4 rows per thread, L2-resident)
    {
        const float* xp = x + ((size_t)b * WL_L * WL_D) + d;
        #pragma unroll
        for (int l = tid; l < WL_L; l += WL_NT)
            xs[l] = xp[(size_t)l * WL_D];
    }
    __syncthreads();

    float g[8], h[8];
    #pragma unroll
    for (int i = 0; i < 8; i++) { g[i] = gs[i]; h[i] = hs[i]; }

    const float4* xs4  = (const float4*)xs;
    const float4* v0s4 = (const float4*)v0s;
    const float4* v1s4 = (const float4*)v1s;
    const float4* v2s4 = (const float4*)v2s;
    float4* xs4w  = (float4*)xs;
    float4* v0s4w = (float4*)v0s;
    float4* v1s4w = (float4*)v1s;
    float4* v2s4w = (float4*)v2s;

    float w0[4], w1[4], w2[4];

    // ── stage 1: dilation 1 on xs → v0 (g→v0s) + w0 (h, regs)
    {
        float4 A = xs4[(tid - 2) & WL_QMASK];
        float4 B = xs4[(tid - 1) & WL_QMASK];
        float4 C = xs4[tid];
        float win[12] = {A.x,A.y,A.z,A.w, B.x,B.y,B.z,B.w, C.x,C.y,C.z,C.w};
        float vg[4] = {0,0,0,0};
        #pragma unroll
        for (int j = 0; j < 4; j++) w0[j] = 0.f;
        #pragma unroll
        for (int i = 0; i < 8; i++) {
            #pragma unroll
            for (int j = 0; j < 4; j++) {
                vg[j] += g[i] * win[8 + j - i];
                w0[j] += h[i] * win[8 + j - i];
            }
        }
        v0s4w[tid] = make_float4(vg[0], vg[1], vg[2], vg[3]);
    }
    __syncthreads();

    // ── stage 2: dilation 2 on v0 → v1 (g→v1s) + w1 (h, regs); park w0 → xs
    {
        float win[20];
        #pragma unroll
        for (int kk = 0; kk < 5; kk++) {
            float4 qv = v0s4[(tid - 4 + kk) & WL_QMASK];
            win[4*kk] = qv.x; win[4*kk+1] = qv.y; win[4*kk+2] = qv.z; win[4*kk+3] = qv.w;
        }
        float vg[4] = {0,0,0,0};
        #pragma unroll
        for (int j = 0; j < 4; j++) w1[j] = 0.f;
        #pragma unroll
        for (int i = 0; i < 8; i++) {
            #pragma unroll
            for (int j = 0; j < 4; j++) {
                vg[j] += g[i] * win[16 + j - 2*i];
                w1[j] += h[i] * win[16 + j - 2*i];
            }
        }
        v1s4w[tid] = make_float4(vg[0], vg[1], vg[2], vg[3]);
        xs4w[tid]  = make_float4(w0[0], w0[1], w0[2], w0[3]);   // xs dead → park w0
    }
    __syncthreads();

    // ── stage 3: dilation 4 on v1 → v2 (g→v2s) + w2 (h, regs); park w1 → v0s
    {
        float vg[4] = {0,0,0,0};
        #pragma unroll
        for (int j = 0; j < 4; j++) w2[j] = 0.f;
        #pragma unroll
        for (int i = 0; i < 8; i++) {
            float4 qv = v1s4[(tid - i) & WL_QMASK];
            vg[0] += g[i] * qv.x; vg[1] += g[i] * qv.y;
            vg[2] += g[i] * qv.z; vg[3] += g[i] * qv.w;
            w2[0] += h[i] * qv.x; w2[1] += h[i] * qv.y;
            w2[2] += h[i] * qv.z; w2[3] += h[i] * qv.w;
        }
        v2s4w[tid] = make_float4(vg[0], vg[1], vg[2], vg[3]);
        v0s4w[tid] = make_float4(w1[0], w1[1], w1[2], w1[3]);   // v0s dead → park w1
    }
    __syncthreads();

    // ── stage 4: dilation 8 on v2 → w3 (h) + v3 (g); unpark w0,w1; emit 5 coeffs
    {
        float w3[4] = {0,0,0,0}, v3[4] = {0,0,0,0};
        #pragma unroll
        for (int i = 0; i < 8; i++) {
            float4 qv = v2s4[(tid - 2*i) & WL_QMASK];
            w3[0] += h[i] * qv.x; w3[1] += h[i] * qv.y;
            w3[2] += h[i] * qv.z; w3[3] += h[i] * qv.w;
            v3[0] += g[i] * qv.x; v3[1] += g[i] * qv.y;
            v3[2] += g[i] * qv.z; v3[3] += g[i] * qv.w;
        }
        float4 w0q = xs4[tid];
        float4 w1q = v0s4[tid];
        float pw0[4] = {w0q.x, w0q.y, w0q.z, w0q.w};
        float pw1[4] = {w1q.x, w1q.y, w1q.z, w1q.w};

        float o[20];
        #pragma unroll
        for (int j = 0; j < 4; j++) {
            o[j*5 + 0] = pw0[j];
            o[j*5 + 1] = pw1[j];
            o[j*5 + 2] = w2[j];
            o[j*5 + 3] = w3[j];
            o[j*5 + 4] = v3[j];
        }
        float4* og = (float4*)(out + ((size_t)bd * WL_L + 4 * tid) * 5);
        #pragma unroll
        for (int kk = 0; kk < 5; kk++) og[kk] = ((const float4*)o)[kk];
    }
}

extern "C" void kernel_launch(void* const* d_in, const int* in_sizes, int n_in,
                              void* d_out, int out_size) {
    const float* x     = (const float*)d_in[0];
    const float* w_dec = (const float*)d_in[1];
    const float* v_dec = (const float*)d_in[2];
    float* out = (float*)d_out;

    wavelet_db4_kernel<<<WL_B * WL_D, WL_NT>>>(x, w_dec, v_dec, out);
}

// round 15
// speedup vs baseline: 1.2569x; 1.2569x over previous
#include <cuda_runtime.h>

#define WL_L      2048
#define WL_LMASK  2047
#define WL_D      32
#define WL_B      16
#define WL_NT     256

#define WL_G      4                   // d-planes per CTA
#define WL_T      256                 // outputs per plane per CTA
#define WL_HALO   112                 // >= 105 back-reach, multiple of 4
#define WL_EXT    (WL_T + WL_HALO)    // 368
#define WL_NCHUNK (WL_L / WL_T)       // 8
#define WL_NDG    (WL_D / WL_G)       // 8

// DB4 taps / sqrt(2), computed exactly as the reference does (double literal
// divided by double sqrt(2)=1.4142135623730951, then cast to float32).
#define SQ2 1.4142135623730951
__device__ __constant__ const float G_[8] = {
    (float)(-0.010597401784997278 / SQ2), (float)( 0.032883011666982945 / SQ2),
    (float)( 0.030841381835986965 / SQ2), (float)(-0.18703481171888114  / SQ2),
    (float)(-0.02798376941698385  / SQ2), (float)( 0.6308807679295904   / SQ2),
    (float)( 0.7148465705525415   / SQ2), (float)( 0.23037781330885523  / SQ2)};
__device__ __constant__ const float H_[8] = {
    (float)(-0.23037781330885523  / SQ2), (float)( 0.7148465705525415   / SQ2),
    (float)(-0.6308807679295904   / SQ2), (float)(-0.02798376941698385  / SQ2),
    (float)( 0.18703481171888114  / SQ2), (float)( 0.030841381835986965 / SQ2),
    (float)(-0.032883011666982945 / SQ2), (float)(-0.010597401784997278 / SQ2)};

// compile-time tap getters (constant-fold into FFMA immediates)
#define GT(i) ((float)(GVALS##i))
__device__ __forceinline__ constexpr float gtap(int i) {
    return i == 0 ? (float)(-0.010597401784997278 / SQ2)
         : i == 1 ? (float)( 0.032883011666982945 / SQ2)
         : i == 2 ? (float)( 0.030841381835986965 / SQ2)
         : i == 3 ? (float)(-0.18703481171888114  / SQ2)
         : i == 4 ? (float)(-0.02798376941698385  / SQ2)
         : i == 5 ? (float)( 0.6308807679295904   / SQ2)
         : i == 6 ? (float)( 0.7148465705525415   / SQ2)
         :          (float)( 0.23037781330885523  / SQ2);
}
__device__ __forceinline__ constexpr float htap(int i) {
    return i == 0 ? (float)(-0.23037781330885523  / SQ2)
         : i == 1 ? (float)( 0.7148465705525415   / SQ2)
         : i == 2 ? (float)(-0.6308807679295904   / SQ2)
         : i == 3 ? (float)(-0.02798376941698385  / SQ2)
         : i == 4 ? (float)( 0.18703481171888114  / SQ2)
         : i == 5 ? (float)( 0.030841381835986965 / SQ2)
         : i == 6 ? (float)(-0.032883011666982945 / SQ2)
         :          (float)(-0.010597401784997278 / SQ2);
}

__global__ __launch_bounds__(WL_NT) void wavelet_db4_kernel(
    const float* __restrict__ x,       // (B, L, D)
    const float* __restrict__ w_dec,   // (4, L, L) — unused (taps are constants)
    const float* __restrict__ v_dec,   // (4, L, L) — unused (taps are constants)
    float* __restrict__ out)           // (B, D, L, 5)
{
    __shared__ __align__(16) float xs [WL_G][WL_EXT];
    __shared__ __align__(16) float v0s[WL_G][WL_EXT];
    __shared__ __align__(16) float v1s[WL_G][WL_EXT];
    __shared__ __align__(16) float v2s[WL_G][WL_EXT];

    const int tid   = threadIdx.x;
    const int blk   = blockIdx.x;
    const int chunk = blk & (WL_NCHUNK - 1);
    const int dg    = (blk >> 3) & (WL_NDG - 1);
    const int b     = blk >> 6;
    const int M0    = chunk * WL_T;
    const int base  = M0 - WL_HALO;

    const int p  = tid >> 6;          // plane 0..3
    const int pq = tid & 63;          // slot in plane 0..63
    const int b4 = 28 + pq;           // this thread's output quad (28..91)
    const int hq = pq - 36;           // halo quad 2..27 on pq 38..63

    // amortized gather: one float4 across 4 adjacent d per x-row
    {
        const float* xp = x + ((size_t)b * WL_L * WL_D) + dg * WL_G;
        #pragma unroll
        for (int l = tid; l < WL_EXT; l += WL_NT) {
            int gl = (base + l) & WL_LMASK;
            float4 qv = *(const float4*)(xp + (size_t)gl * WL_D);
            xs[0][l] = qv.x; xs[1][l] = qv.y; xs[2][l] = qv.z; xs[3][l] = qv.w;
        }
    }
    __syncthreads();

    const float4* xs4  = (const float4*)(&xs [p][0]);
    const float4* v0s4 = (const float4*)(&v0s[p][0]);
    const float4* v1s4 = (const float4*)(&v1s[p][0]);
    const float4* v2s4 = (const float4*)(&v2s[p][0]);
    float4* v0s4w = (float4*)(&v0s[p][0]);
    float4* v1s4w = (float4*)(&v1s[p][0]);
    float4* v2s4w = (float4*)(&v2s[p][0]);

    float w0[4], w1[4], w2[4];

    // ── stage 1: dilation 1 on xs → v0 (g) + w0 (h), window loaded once
    {
        int wb = b4 - 2;
        float4 A = xs4[wb], B = xs4[wb + 1], C = xs4[wb + 2];
        float win[12] = {A.x,A.y,A.z,A.w, B.x,B.y,B.z,B.w, C.x,C.y,C.z,C.w};
        float vg[4] = {0,0,0,0};
        #pragma unroll
        for (int j = 0; j < 4; j++) w0[j] = 0.f;
        #pragma unroll
        for (int i = 0; i < 8; i++) {
            #pragma unroll
            for (int j = 0; j < 4; j++) {
                vg[j] += gtap(i) * win[8 + j - i];
                w0[j] += htap(i) * win[8 + j - i];
            }
        }
        v0s4w[b4] = make_float4(vg[0], vg[1], vg[2], vg[3]);

        if (hq >= 2) {                // halo v0 (g only), quads 2..27
            int wbh = hq - 2;
            float4 HA = xs4[wbh], HB = xs4[wbh + 1], HC = xs4[wbh + 2];
            float hw[12] = {HA.x,HA.y,HA.z,HA.w, HB.x,HB.y,HB.z,HB.w, HC.x,HC.y,HC.z,HC.w};
            float a0=0.f, a1=0.f, a2=0.f, a3=0.f;
            #pragma unroll
            for (int i = 0; i < 8; i++) {
                a0 += gtap(i) * hw[ 8 - i]; a1 += gtap(i) * hw[ 9 - i];
                a2 += gtap(i) * hw[10 - i]; a3 += gtap(i) * hw[11 - i];
            }
            v0s4w[hq] = make_float4(a0, a1, a2, a3);
        }
    }
    __syncthreads();

    // ── stage 2: dilation 2 on v0 → v1 (g) + w1 (h)
    {
        int wb = b4 - 4;
        float win[20];
        #pragma unroll
        for (int kk = 0; kk < 5; kk++) {
            float4 qv = v0s4[wb + kk];
            win[4*kk] = qv.x; win[4*kk+1] = qv.y; win[4*kk+2] = qv.z; win[4*kk+3] = qv.w;
        }
        float vg[4] = {0,0,0,0};
        #pragma unroll
        for (int j = 0; j < 4; j++) w1[j] = 0.f;
        #pragma unroll
        for (int i = 0; i < 8; i++) {
            #pragma unroll
            for (int j = 0; j < 4; j++) {
                vg[j] += gtap(i) * win[16 + j - 2*i];
                w1[j] += htap(i) * win[16 + j - 2*i];
            }
        }
        v1s4w[b4] = make_float4(vg[0], vg[1], vg[2], vg[3]);

        if (hq >= 7) {                // halo v1 (g only), quads 7..27
            int wbh = hq - 4;
            float hw[20];
            #pragma unroll
            for (int kk = 0; kk < 5; kk++) {
                float4 qv = v0s4[wbh + kk];
                hw[4*kk] = qv.x; hw[4*kk+1] = qv.y; hw[4*kk+2] = qv.z; hw[4*kk+3] = qv.w;
            }
            float a0=0.f, a1=0.f, a2=0.f, a3=0.f;
            #pragma unroll
            for (int i = 0; i < 8; i++) {
                a0 += gtap(i) * hw[16 - 2*i]; a1 += gtap(i) * hw[17 - 2*i];
                a2 += gtap(i) * hw[18 - 2*i]; a3 += gtap(i) * hw[19 - 2*i];
            }
            v1s4w[hq] = make_float4(a0, a1, a2, a3);
        }
    }
    __syncthreads();

    // ── stage 3: dilation 4 on v1 → v2 (g) + w2 (h); one float4 per tap
    {
        float vg[4] = {0,0,0,0};
        #pragma unroll
        for (int j = 0; j < 4; j++) w2[j] = 0.f;
        #pragma unroll
        for (int i = 0; i < 8; i++) {
            float4 qv = v1s4[b4 - i];
            vg[0] += gtap(i) * qv.x; vg[1] += gtap(i) * qv.y;
            vg[2] += gtap(i) * qv.z; vg[3] += gtap(i) * qv.w;
            w2[0] += htap(i) * qv.x; w2[1] += htap(i) * qv.y;
            w2[2] += htap(i) * qv.z; w2[3] += htap(i) * qv.w;
        }
        v2s4w[b4] = make_float4(vg[0], vg[1], vg[2], vg[3]);

        if (hq >= 14) {               // halo v2 (g only), quads 14..27
            float a0=0.f, a1=0.f, a2=0.f, a3=0.f;
            #pragma unroll
            for (int i = 0; i < 8; i++) {
                float4 qv = v1s4[hq - i];
                a0 += gtap(i) * qv.x; a1 += gtap(i) * qv.y;
                a2 += gtap(i) * qv.z; a3 += gtap(i) * qv.w;
            }
            v2s4w[hq] = make_float4(a0, a1, a2, a3);
        }
    }
    __syncthreads();

    // ── stage 4: dilation 8 on v2 → w3 (h) + v3 (g); write all 5 coeffs
    {
        float w3[4] = {0,0,0,0}, v3[4] = {0,0,0,0};
        #pragma unroll
        for (int i = 0; i < 8; i++) {
            float4 qv = v2s4[b4 - 2*i];
            w3[0] += htap(i) * qv.x; w3[1] += htap(i) * qv.y;
            w3[2] += htap(i) * qv.z; w3[3] += htap(i) * qv.w;
            v3[0] += gtap(i) * qv.x; v3[1] += gtap(i) * qv.y;
            v3[2] += gtap(i) * qv.z; v3[3] += gtap(i) * qv.w;
        }

        float o[20];
        #pragma unroll
        for (int j = 0; j < 4; j++) {
            o[j*5 + 0] = w0[j];
            o[j*5 + 1] = w1[j];
            o[j*5 + 2] = w2[j];
            o[j*5 + 3] = w3[j];
            o[j*5 + 4] = v3[j];
        }
        const int bd = b * WL_D + dg * WL_G + p;
        const int m0 = M0 + 4 * pq;
        float4* og = (float4*)(out + ((size_t)bd * WL_L + m0) * 5);
        #pragma unroll
        for (int kk = 0; kk < 5; kk++) og[kk] = ((const float4*)o)[kk];
    }
}

extern "C" void kernel_launch(void* const* d_in, const int* in_sizes, int n_in,
                              void* d_out, int out_size) {
    const float* x     = (const float*)d_in[0];
    const float* w_dec = (const float*)d_in[1];
    const float* v_dec = (const float*)d_in[2];
    float* out = (float*)d_out;

    wavelet_db4_kernel<<<WL_B * WL_NDG * WL_NCHUNK, WL_NT>>>(x, w_dec, v_dec, out);
}